// round 8
// baseline (speedup 1.0000x reference)
#include <cuda_runtime.h>
#include <cuda_fp16.h>
#include <cstdint>

#define B_  64
#define NI  2048
#define DI  16
#define NO  32
#define DO  32
#define CH  16            // i-chunks per (b) for round partials
#define IC  (NI / CH)     // 128 i per chunk

// u_hat layout: [b][i][od(1024)] fp16, 268 MB
__device__ __half g_uhat[(size_t)B_ * NI * NO * DO];
__device__ float  g_part[B_ * CH * NO * DO];
__device__ float  g_vsum[B_ * NO * DO];

// ---------------------------------------------------------------------------
// K1 (tensor): per i, C[b=64, od=1024] = x_i[64,16] @ W_i[16,1024] via
// mma.sync.m16n8k8 tf32. CTA per i, 256 threads = 8 warps; warp w owns
// od in [w*128, (w+1)*128) as 16 n8-tiles. A (x) frags held in regs across
// all tiles; B (W) loaded directly from global (k-split covers full rows).
// ---------------------------------------------------------------------------
__global__ __launch_bounds__(256, 1)
void k1_tensor(const float* __restrict__ x, const float* __restrict__ W) {
    const int i = blockIdx.x;
    const int t = threadIdx.x;
    const int w = t >> 5, lane = t & 31;
    const int g = lane >> 2, tg = lane & 3;    // quad group / thread-in-group

    __shared__ unsigned xs[64 * 20 + 4];       // x as tf32 bits, rows padded to 20

    // stage x[b, i, 0..15] -> smem (tf32-rounded), fully coalesced
    {
        const int b = t >> 2, k4 = (t & 3) << 2;
        const float4 v = *reinterpret_cast<const float4*>(
            x + ((size_t)b * NI + i) * DI + k4);
        unsigned r0, r1, r2, r3;
        asm("cvt.rna.tf32.f32 %0, %1;" : "=r"(r0) : "f"(v.x));
        asm("cvt.rna.tf32.f32 %0, %1;" : "=r"(r1) : "f"(v.y));
        asm("cvt.rna.tf32.f32 %0, %1;" : "=r"(r2) : "f"(v.z));
        asm("cvt.rna.tf32.f32 %0, %1;" : "=r"(r3) : "f"(v.w));
        unsigned* p = &xs[b * 20 + k4];
        p[0] = r0; p[1] = r1; p[2] = r2; p[3] = r3;
    }
    __syncthreads();

    // A fragments: 4 m-tiles (b 0..63) x 2 k-steps x 4 regs, reused over n
    unsigned a[4][2][4];
    #pragma unroll
    for (int mt = 0; mt < 4; mt++) {
        const int r0 = mt * 16 + g;
        #pragma unroll
        for (int ks = 0; ks < 2; ks++) {
            const int c0 = ks * 8 + tg;
            a[mt][ks][0] = xs[r0 * 20 + c0];
            a[mt][ks][1] = xs[(r0 + 8) * 20 + c0];
            a[mt][ks][2] = xs[r0 * 20 + c0 + 4];
            a[mt][ks][3] = xs[(r0 + 8) * 20 + c0 + 4];
        }
    }

    __half2* outb = reinterpret_cast<__half2*>(g_uhat) + (size_t)i * 512;
    const size_t bstride = (size_t)NI * 512;   // half2 stride per b

    #pragma unroll 4
    for (int nt = 0; nt < 16; nt++) {
        const int tilebase = w * 128 + nt * 8;
        const int od = tilebase + g;           // this thread's B column (n)
        // W row for (o = od>>5, i, d = od&31): 16 contiguous floats
        const float* wrow = W + ((size_t)(od >> 5) * NI + i) * 512 + (od & 31) * 16;
        unsigned b0k0, b1k0, b0k1, b1k1;
        asm("cvt.rna.tf32.f32 %0, %1;" : "=r"(b0k0) : "f"(wrow[tg]));
        asm("cvt.rna.tf32.f32 %0, %1;" : "=r"(b1k0) : "f"(wrow[tg + 4]));
        asm("cvt.rna.tf32.f32 %0, %1;" : "=r"(b0k1) : "f"(wrow[tg + 8]));
        asm("cvt.rna.tf32.f32 %0, %1;" : "=r"(b1k1) : "f"(wrow[tg + 12]));

        const int odp = (tilebase >> 1) + tg;  // half2 offset of this thread's od pair
        #pragma unroll
        for (int mt = 0; mt < 4; mt++) {
            float c0 = 0.f, c1 = 0.f, c2 = 0.f, c3 = 0.f;
            asm volatile(
                "mma.sync.aligned.m16n8k8.row.col.f32.tf32.tf32.f32 "
                "{%0,%1,%2,%3}, {%4,%5,%6,%7}, {%8,%9}, {%0,%1,%2,%3};"
                : "+f"(c0), "+f"(c1), "+f"(c2), "+f"(c3)
                : "r"(a[mt][0][0]), "r"(a[mt][0][1]),
                  "r"(a[mt][0][2]), "r"(a[mt][0][3]),
                  "r"(b0k0), "r"(b1k0));
            asm volatile(
                "mma.sync.aligned.m16n8k8.row.col.f32.tf32.tf32.f32 "
                "{%0,%1,%2,%3}, {%4,%5,%6,%7}, {%8,%9}, {%0,%1,%2,%3};"
                : "+f"(c0), "+f"(c1), "+f"(c2), "+f"(c3)
                : "r"(a[mt][1][0]), "r"(a[mt][1][1]),
                  "r"(a[mt][1][2]), "r"(a[mt][1][3]),
                  "r"(b0k1), "r"(b1k1));
            // c0,c1 -> (b = mt*16+g, od = tilebase+2tg, +1); c2,c3 -> b+8
            const int brow = mt * 16 + g;
            outb[(size_t)brow * bstride + odp]       = __floats2half2_rn(c0, c1);
            outb[(size_t)(brow + 8) * bstride + odp] = __floats2half2_rn(c2, c3);
        }
    }
}

// ---------------------------------------------------------------------------
// Routing round (verbatim from the 295.7us config). CTA = (chunk, b), 256 thr.
// Warp covers 8 o x 4 q (q owns 8 d); halves split the 8-i batch.
// ---------------------------------------------------------------------------
__global__ __launch_bounds__(256)
void k_round(int use_vsum) {
    const int ch = blockIdx.x, b = blockIdx.y;
    const int t = threadIdx.x;
    const int w = t >> 5, lane = t & 31;
    const int o = ((w & 3) << 3) + (lane >> 2);
    const int q = lane & 3;                 // owns d = 8q .. 8q+7
    const int half = w >> 2;                // i-subgroup within batch

    float vs[8];
    if (use_vsum) {
        const float4* vp = reinterpret_cast<const float4*>(
            g_vsum + (b * NO + o) * DO + q * 8);
        float4 va = vp[0], vb = vp[1];
        vs[0]=va.x; vs[1]=va.y; vs[2]=va.z; vs[3]=va.w;
        vs[4]=vb.x; vs[5]=vb.y; vs[6]=vb.z; vs[7]=vb.w;
    }

    float sp[8];
    #pragma unroll
    for (int d = 0; d < 8; d++) sp[d] = 0.f;

    __shared__ float s_db[8][NO];
    __shared__ float s_c[8][NO];

    // uint4 = 8 halves; 128 uint4 per i
    const uint4* up = reinterpret_cast<const uint4*>(g_uhat) +
                      ((size_t)b * NI + (size_t)ch * IC) * 128 + o * 4 + q;

    #pragma unroll 1
    for (int ib = 0; ib < IC; ib += 8) {
        uint4 raw[4];
        #pragma unroll
        for (int v = 0; v < 4; v++)
            raw[v] = up[(size_t)(ib + half * 4 + v) * 128];

        float F[4][8];
        #pragma unroll
        for (int v = 0; v < 4; v++) {
            float2 fa = __half22float2(*reinterpret_cast<__half2*>(&raw[v].x));
            float2 fb = __half22float2(*reinterpret_cast<__half2*>(&raw[v].y));
            float2 fc = __half22float2(*reinterpret_cast<__half2*>(&raw[v].z));
            float2 fd = __half22float2(*reinterpret_cast<__half2*>(&raw[v].w));
            F[v][0]=fa.x; F[v][1]=fa.y; F[v][2]=fb.x; F[v][3]=fb.y;
            F[v][4]=fc.x; F[v][5]=fc.y; F[v][6]=fd.x; F[v][7]=fd.y;
        }

        if (use_vsum) {
            #pragma unroll
            for (int v = 0; v < 4; v++) {
                float tdb = F[v][0]*vs[0] + F[v][1]*vs[1] + F[v][2]*vs[2] +
                            F[v][3]*vs[3] + F[v][4]*vs[4] + F[v][5]*vs[5] +
                            F[v][6]*vs[6] + F[v][7]*vs[7];
                tdb += __shfl_xor_sync(0xffffffffu, tdb, 2);
                tdb += __shfl_xor_sync(0xffffffffu, tdb, 1);
                if (q == 0) s_db[half * 4 + v][o] = tdb;
            }
            __syncthreads();
            {
                float db = s_db[w][lane];
                float m = db;
                #pragma unroll
                for (int st = 16; st; st >>= 1)
                    m = fmaxf(m, __shfl_xor_sync(0xffffffffu, m, st));
                float e = __expf(db - m);
                float sm = e;
                #pragma unroll
                for (int st = 16; st; st >>= 1)
                    sm += __shfl_xor_sync(0xffffffffu, sm, st);
                s_c[w][lane] = e / sm;
            }
            __syncthreads();
            #pragma unroll
            for (int v = 0; v < 4; v++) {
                float c = s_c[half * 4 + v][o];
                #pragma unroll
                for (int d = 0; d < 8; d++) sp[d] += c * F[v][d];
            }
        } else {
            #pragma unroll
            for (int v = 0; v < 4; v++)
                #pragma unroll
                for (int d = 0; d < 8; d++) sp[d] += F[v][d];
        }
    }

    if (!use_vsum) {
        const float c = 1.0f / (float)NO;
        #pragma unroll
        for (int d = 0; d < 8; d++) sp[d] *= c;
    }

    __shared__ float s_red[256 * 8];
    #pragma unroll
    for (int d = 0; d < 8; d++)
        s_red[(t & 127) * 8 + d + (half ? 1024 : 0)] = sp[d];
    __syncthreads();
    if (half == 0) {
        float4* pp = reinterpret_cast<float4*>(
            g_part + ((b * CH + ch) * (NO * DO)) + o * DO + q * 8);
        float4 r0, r1;
        int base = (t & 127) * 8;
        r0.x = s_red[base+0] + s_red[base+0+1024];
        r0.y = s_red[base+1] + s_red[base+1+1024];
        r0.z = s_red[base+2] + s_red[base+2+1024];
        r0.w = s_red[base+3] + s_red[base+3+1024];
        r1.x = s_red[base+4] + s_red[base+4+1024];
        r1.y = s_red[base+5] + s_red[base+5+1024];
        r1.z = s_red[base+6] + s_red[base+6+1024];
        r1.w = s_red[base+7] + s_red[base+7+1024];
        pp[0] = r0; pp[1] = r1;
    }
}

// ---------------------------------------------------------------------------
// Stage 2 (verbatim): reduce chunk partials -> s, squash -> v, update vsum/out.
// ---------------------------------------------------------------------------
__global__ __launch_bounds__(1024)
void k_stage2(float* __restrict__ out, int round) {
    const int b = blockIdx.x, t = threadIdx.x;
    float s = 0.f;
    #pragma unroll
    for (int c = 0; c < CH; c++)
        s += g_part[(b * CH + c) * (NO * DO) + t];

    float sq = s * s;
    #pragma unroll
    for (int st = 16; st; st >>= 1)
        sq += __shfl_xor_sync(0xffffffffu, sq, st);

    float scale = sq / (1.0f + sq) * rsqrtf(sq + 1e-7f);
    float v = s * scale;

    int idx = b * (NO * DO) + t;
    if (round == 2)      out[idx] = v;
    else if (round == 0) g_vsum[idx] = v;
    else                 g_vsum[idx] += v;
}

// ---------------------------------------------------------------------------
extern "C" void kernel_launch(void* const* d_in, const int* in_sizes, int n_in,
                              void* d_out, int out_size) {
    const float* x = (const float*)d_in[0];
    const float* W = (const float*)d_in[1];
    if (in_sizes[0] != B_ * NI * DI) {
        x = (const float*)d_in[1];
        W = (const float*)d_in[0];
    }
    float* out = (float*)d_out;

    k1_tensor<<<NI, 256>>>(x, W);

    dim3 rg(CH, B_);
    k_round<<<rg, 256>>>(0);
    k_stage2<<<B_, NO * DO>>>(out, 0);
    k_round<<<rg, 256>>>(1);
    k_stage2<<<B_, NO * DO>>>(out, 1);
    k_round<<<rg, 256>>>(2);
    k_stage2<<<B_, NO * DO>>>(out, 2);
}

// round 9
// speedup vs baseline: 1.5517x; 1.5517x over previous
#include <cuda_runtime.h>
#include <cuda_fp16.h>
#include <cstdint>

#define B_  64
#define NI  2048
#define DI  16
#define NO  32
#define DO  32
#define CH  16            // i-chunks per (b) for round partials
#define IC  (NI / CH)     // 128 i per chunk

// u_hat layout: [b][i][od(1024)] fp16, 268 MB
__device__ __half g_uhat[(size_t)B_ * NI * NO * DO];
__device__ float  g_part[B_ * CH * NO * DO];
__device__ float  g_vsum[B_ * NO * DO];

// ---------- packed f32x2 helpers ----------
__device__ __forceinline__ unsigned long long splat2(float v) {
    unsigned long long r;
    asm("mov.b64 %0, {%1, %1};" : "=l"(r) : "f"(v));
    return r;
}
__device__ __forceinline__ unsigned long long pack2(float x, float y) {
    unsigned long long r;
    asm("mov.b64 %0, {%1, %2};" : "=l"(r) : "f"(x), "f"(y));
    return r;
}
__device__ __forceinline__ void ffma2(unsigned long long &d,
                                      unsigned long long a, unsigned long long b) {
    asm("fma.rn.f32x2 %0, %1, %2, %0;" : "+l"(d) : "l"(a), "l"(b));
}
__device__ __forceinline__ void add2(unsigned long long &d, unsigned long long a) {
    asm("add.rn.f32x2 %0, %0, %1;" : "+l"(d) : "l"(a));
}
__device__ __forceinline__ float2 unpack2(unsigned long long v) {
    float2 f;
    asm("mov.b64 {%0, %1}, %2;" : "=f"(f.x), "=f"(f.y) : "l"(v));
    return f;
}

// ---------------------------------------------------------------------------
// K1 (FFMA2, proven ~110us): u_hat[b][i][od] = sum_k W[o][i][d][k] * x[b][i][k]
// ---------------------------------------------------------------------------
__global__ __launch_bounds__(512, 1)
void k1_uhat(const float* __restrict__ x, const float* __restrict__ W) {
    const int i = blockIdx.x;
    const int t = threadIdx.x;

    __shared__ __align__(16) float xs[DI][B_];
    {
        int idx = t;
        #pragma unroll
        for (int r = 0; r < 2; r++, idx += 512) {
            int b = idx >> 4, k = idx & 15;
            xs[k][b] = x[((size_t)b * NI + i) * DI + k];
        }
    }

    const int o = t >> 4, dp = t & 15;           // d = 2dp, 2dp+1
    const float4* wp = reinterpret_cast<const float4*>(W) +
                       ((((size_t)o * NI + i) * DO + 2 * dp) * DI >> 2);
    float4 qa = wp[0], qb = wp[1], qc = wp[2], qd = wp[3];
    float4 qe = wp[4], qf = wp[5], qg = wp[6], qh = wp[7];

    unsigned long long w0[16], w1[16];
    w0[0]=splat2(qa.x); w0[1]=splat2(qa.y); w0[2]=splat2(qa.z); w0[3]=splat2(qa.w);
    w0[4]=splat2(qb.x); w0[5]=splat2(qb.y); w0[6]=splat2(qb.z); w0[7]=splat2(qb.w);
    w0[8]=splat2(qc.x); w0[9]=splat2(qc.y); w0[10]=splat2(qc.z); w0[11]=splat2(qc.w);
    w0[12]=splat2(qd.x); w0[13]=splat2(qd.y); w0[14]=splat2(qd.z); w0[15]=splat2(qd.w);
    w1[0]=splat2(qe.x); w1[1]=splat2(qe.y); w1[2]=splat2(qe.z); w1[3]=splat2(qe.w);
    w1[4]=splat2(qf.x); w1[5]=splat2(qf.y); w1[6]=splat2(qf.z); w1[7]=splat2(qf.w);
    w1[8]=splat2(qg.x); w1[9]=splat2(qg.y); w1[10]=splat2(qg.z); w1[11]=splat2(qg.w);
    w1[12]=splat2(qh.x); w1[13]=splat2(qh.y); w1[14]=splat2(qh.z); w1[15]=splat2(qh.w);

    __syncthreads();

    __half2* ob = reinterpret_cast<__half2*>(g_uhat) +
                  (size_t)i * 512 + o * 16 + dp;
    const size_t bs2 = (size_t)NI * 512;

    #pragma unroll 1
    for (int bq = 0; bq < 16; bq++) {
        const int b = bq * 4;
        unsigned long long a0p = 0ull, a0q = 0ull;
        unsigned long long a1p = 0ull, a1q = 0ull;
        #pragma unroll
        for (int k = 0; k < 16; k++) {
            ulonglong2 xq = *reinterpret_cast<const ulonglong2*>(&xs[k][b]);
            ffma2(a0p, w0[k], xq.x);
            ffma2(a0q, w0[k], xq.y);
            ffma2(a1p, w1[k], xq.x);
            ffma2(a1q, w1[k], xq.y);
        }
        float2 f0p = unpack2(a0p), f0q = unpack2(a0q);
        float2 f1p = unpack2(a1p), f1q = unpack2(a1q);
        ob[(size_t)(b + 0) * bs2] = __float22half2_rn(make_float2(f0p.x, f1p.x));
        ob[(size_t)(b + 1) * bs2] = __float22half2_rn(make_float2(f0p.y, f1p.y));
        ob[(size_t)(b + 2) * bs2] = __float22half2_rn(make_float2(f0q.x, f1q.x));
        ob[(size_t)(b + 3) * bs2] = __float22half2_rn(make_float2(f0q.y, f1q.y));
    }
}

// ---------------------------------------------------------------------------
// Round 0 dedicated: s0 partial = (1/32) * sum_i u_hat[b][i][od]  (pure stream)
// CTA = (ch, b), 256 threads. slot = t&127 picks 8 od's (uint4); half = t>>7
// splits the 128 i's. No smem / barriers in the loop. Tail combine == k_round.
// ---------------------------------------------------------------------------
__global__ __launch_bounds__(256)
void k_round0() {
    const int ch = blockIdx.x, b = blockIdx.y;
    const int t = threadIdx.x;
    const int slot = t & 127, half = t >> 7;

    const uint4* up = reinterpret_cast<const uint4*>(g_uhat) +
                      ((size_t)b * NI + (size_t)ch * IC + half * 64) * 128 + slot;

    unsigned long long sp2[4] = {0ull, 0ull, 0ull, 0ull};

    #pragma unroll 1
    for (int ig = 0; ig < 64; ig += 8) {
        uint4 raw[8];
        #pragma unroll
        for (int v = 0; v < 8; v++)
            raw[v] = up[(size_t)(ig + v) * 128];
        #pragma unroll
        for (int v = 0; v < 8; v++) {
            const unsigned* ru = reinterpret_cast<const unsigned*>(&raw[v]);
            #pragma unroll
            for (int p = 0; p < 4; p++) {
                float2 f = __half22float2(*reinterpret_cast<const __half2*>(&ru[p]));
                add2(sp2[p], pack2(f.x, f.y));
            }
        }
    }

    float sp[8];
    {
        float2 f0 = unpack2(sp2[0]), f1 = unpack2(sp2[1]);
        float2 f2 = unpack2(sp2[2]), f3 = unpack2(sp2[3]);
        const float c = 1.0f / (float)NO;
        sp[0]=f0.x*c; sp[1]=f0.y*c; sp[2]=f1.x*c; sp[3]=f1.y*c;
        sp[4]=f2.x*c; sp[5]=f2.y*c; sp[6]=f3.x*c; sp[7]=f3.y*c;
    }

    __shared__ float s_red[2048];
    #pragma unroll
    for (int d = 0; d < 8; d++)
        s_red[slot * 8 + d + (half ? 1024 : 0)] = sp[d];
    __syncthreads();
    if (half == 0) {
        float4* pp = reinterpret_cast<float4*>(
            g_part + ((b * CH + ch) * (NO * DO)) + slot * 8);
        int base = slot * 8;
        float4 r0, r1;
        r0.x = s_red[base+0] + s_red[base+0+1024];
        r0.y = s_red[base+1] + s_red[base+1+1024];
        r0.z = s_red[base+2] + s_red[base+2+1024];
        r0.w = s_red[base+3] + s_red[base+3+1024];
        r1.x = s_red[base+4] + s_red[base+4+1024];
        r1.y = s_red[base+5] + s_red[base+5+1024];
        r1.z = s_red[base+6] + s_red[base+6+1024];
        r1.w = s_red[base+7] + s_red[base+7+1024];
        pp[0] = r0; pp[1] = r1;
    }
}

// ---------------------------------------------------------------------------
// Routing rounds 1/2 (verbatim R3/R8, proven 60.1us).
// ---------------------------------------------------------------------------
__global__ __launch_bounds__(256)
void k_round(int use_vsum) {
    const int ch = blockIdx.x, b = blockIdx.y;
    const int t = threadIdx.x;
    const int w = t >> 5, lane = t & 31;
    const int o = ((w & 3) << 3) + (lane >> 2);
    const int q = lane & 3;
    const int half = w >> 2;

    float vs[8];
    if (use_vsum) {
        const float4* vp = reinterpret_cast<const float4*>(
            g_vsum + (b * NO + o) * DO + q * 8);
        float4 va = vp[0], vb = vp[1];
        vs[0]=va.x; vs[1]=va.y; vs[2]=va.z; vs[3]=va.w;
        vs[4]=vb.x; vs[5]=vb.y; vs[6]=vb.z; vs[7]=vb.w;
    }

    float sp[8];
    #pragma unroll
    for (int d = 0; d < 8; d++) sp[d] = 0.f;

    __shared__ float s_db[8][NO];
    __shared__ float s_c[8][NO];

    const uint4* up = reinterpret_cast<const uint4*>(g_uhat) +
                      ((size_t)b * NI + (size_t)ch * IC) * 128 + o * 4 + q;

    #pragma unroll 1
    for (int ib = 0; ib < IC; ib += 8) {
        uint4 raw[4];
        #pragma unroll
        for (int v = 0; v < 4; v++)
            raw[v] = up[(size_t)(ib + half * 4 + v) * 128];

        float F[4][8];
        #pragma unroll
        for (int v = 0; v < 4; v++) {
            float2 fa = __half22float2(*reinterpret_cast<__half2*>(&raw[v].x));
            float2 fb = __half22float2(*reinterpret_cast<__half2*>(&raw[v].y));
            float2 fc = __half22float2(*reinterpret_cast<__half2*>(&raw[v].z));
            float2 fd = __half22float2(*reinterpret_cast<__half2*>(&raw[v].w));
            F[v][0]=fa.x; F[v][1]=fa.y; F[v][2]=fb.x; F[v][3]=fb.y;
            F[v][4]=fc.x; F[v][5]=fc.y; F[v][6]=fd.x; F[v][7]=fd.y;
        }

        if (use_vsum) {
            #pragma unroll
            for (int v = 0; v < 4; v++) {
                float tdb = F[v][0]*vs[0] + F[v][1]*vs[1] + F[v][2]*vs[2] +
                            F[v][3]*vs[3] + F[v][4]*vs[4] + F[v][5]*vs[5] +
                            F[v][6]*vs[6] + F[v][7]*vs[7];
                tdb += __shfl_xor_sync(0xffffffffu, tdb, 2);
                tdb += __shfl_xor_sync(0xffffffffu, tdb, 1);
                if (q == 0) s_db[half * 4 + v][o] = tdb;
            }
            __syncthreads();
            {
                float db = s_db[w][lane];
                float m = db;
                #pragma unroll
                for (int st = 16; st; st >>= 1)
                    m = fmaxf(m, __shfl_xor_sync(0xffffffffu, m, st));
                float e = __expf(db - m);
                float sm = e;
                #pragma unroll
                for (int st = 16; st; st >>= 1)
                    sm += __shfl_xor_sync(0xffffffffu, sm, st);
                s_c[w][lane] = e / sm;
            }
            __syncthreads();
            #pragma unroll
            for (int v = 0; v < 4; v++) {
                float c = s_c[half * 4 + v][o];
                #pragma unroll
                for (int d = 0; d < 8; d++) sp[d] += c * F[v][d];
            }
        } else {
            #pragma unroll
            for (int v = 0; v < 4; v++)
                #pragma unroll
                for (int d = 0; d < 8; d++) sp[d] += F[v][d];
        }
    }

    if (!use_vsum) {
        const float c = 1.0f / (float)NO;
        #pragma unroll
        for (int d = 0; d < 8; d++) sp[d] *= c;
    }

    __shared__ float s_red[256 * 8];
    #pragma unroll
    for (int d = 0; d < 8; d++)
        s_red[(t & 127) * 8 + d + (half ? 1024 : 0)] = sp[d];
    __syncthreads();
    if (half == 0) {
        float4* pp = reinterpret_cast<float4*>(
            g_part + ((b * CH + ch) * (NO * DO)) + o * DO + q * 8);
        float4 r0, r1;
        int base = (t & 127) * 8;
        r0.x = s_red[base+0] + s_red[base+0+1024];
        r0.y = s_red[base+1] + s_red[base+1+1024];
        r0.z = s_red[base+2] + s_red[base+2+1024];
        r0.w = s_red[base+3] + s_red[base+3+1024];
        r1.x = s_red[base+4] + s_red[base+4+1024];
        r1.y = s_red[base+5] + s_red[base+5+1024];
        r1.z = s_red[base+6] + s_red[base+6+1024];
        r1.w = s_red[base+7] + s_red[base+7+1024];
        pp[0] = r0; pp[1] = r1;
    }
}

// ---------------------------------------------------------------------------
// Stage 2 (verbatim): reduce chunk partials -> s, squash -> v, update vsum/out.
// ---------------------------------------------------------------------------
__global__ __launch_bounds__(1024)
void k_stage2(float* __restrict__ out, int round) {
    const int b = blockIdx.x, t = threadIdx.x;
    float s = 0.f;
    #pragma unroll
    for (int c = 0; c < CH; c++)
        s += g_part[(b * CH + c) * (NO * DO) + t];

    float sq = s * s;
    #pragma unroll
    for (int st = 16; st; st >>= 1)
        sq += __shfl_xor_sync(0xffffffffu, sq, st);

    float scale = sq / (1.0f + sq) * rsqrtf(sq + 1e-7f);
    float v = s * scale;

    int idx = b * (NO * DO) + t;
    if (round == 2)      out[idx] = v;
    else if (round == 0) g_vsum[idx] = v;
    else                 g_vsum[idx] += v;
}

// ---------------------------------------------------------------------------
extern "C" void kernel_launch(void* const* d_in, const int* in_sizes, int n_in,
                              void* d_out, int out_size) {
    const float* x = (const float*)d_in[0];
    const float* W = (const float*)d_in[1];
    if (in_sizes[0] != B_ * NI * DI) {
        x = (const float*)d_in[1];
        W = (const float*)d_in[0];
    }
    float* out = (float*)d_out;

    k1_uhat<<<NI, 512>>>(x, W);

    dim3 rg(CH, B_);
    k_round0<<<rg, 256>>>();
    k_stage2<<<B_, NO * DO>>>(out, 0);
    k_round<<<rg, 256>>>(1);
    k_stage2<<<B_, NO * DO>>>(out, 1);
    k_round<<<rg, 256>>>(2);
    k_stage2<<<B_, NO * DO>>>(out, 2);
}